// round 1
// baseline (speedup 1.0000x reference)
#include <cuda_runtime.h>
#include <cstdint>

#define KPOLY 3
#define NN 10000
#define SPLITS 12            // 4 m-splits per k
#define MTOT (NN / 4)        // 2500 inner steps per split

// Scratch (static device arrays; no allocation allowed)
__device__ float g_T1[(size_t)KPOLY * NN * 64];
__device__ float g_P1[(size_t)SPLITS * NN * 64];
__device__ float g_T2[(size_t)KPOLY * NN * 32];
__device__ float g_P2[(size_t)SPLITS * NN * 32];

// ---- packed f32x2 helpers (full-rate fp32 on sm_103a) ----
__device__ __forceinline__ unsigned long long pk2(float a, float b) {
    unsigned long long r;
    asm("mov.b64 %0, {%1,%2};" : "=l"(r) : "f"(a), "f"(b));
    return r;
}
__device__ __forceinline__ unsigned long long f2(unsigned long long a,
                                                 unsigned long long b,
                                                 unsigned long long c) {
    unsigned long long d;
    asm("fma.rn.f32x2 %0, %1, %2, %3;" : "=l"(d) : "l"(a), "l"(b), "l"(c));
    return d;
}

template <int COLS> __device__ __forceinline__ float* Tbuf();
template <> __device__ __forceinline__ float* Tbuf<64>() { return g_T1; }
template <> __device__ __forceinline__ float* Tbuf<32>() { return g_T2; }
template <int COLS> __device__ __forceinline__ float* Pbuf();
template <> __device__ __forceinline__ float* Pbuf<64>() { return g_P1; }
template <> __device__ __forceinline__ float* Pbuf<32>() { return g_P2; }

// =======================================================================
// Main kernel: partial[split] = poly_slice @ T_slice   (split-K, no atomics)
// Block tile: 128 rows x COLS cols; thread tile 4x8 (16 f32x2 accumulators)
// =======================================================================
template <int COLS>
__global__ void __launch_bounds__((128 / 4) * (COLS / 8), 2)
poly_apply_kernel(const float* __restrict__ poly) {
    constexpr int BROWS = 128, MCH = 32, RP = 140;  // RP: pad -> conflict-free, 16B aligned
    constexpr int THREADS = (BROWS / 4) * (COLS / 8);
    constexpr int RSTEP = THREADS / 8;

    __shared__ float sp[MCH * RP];    // poly chunk, transposed: sp[m*RP + row]
    __shared__ float st[MCH * COLS];  // T chunk: st[m*COLS + c]

    const int tid = threadIdx.x;
    const int split = blockIdx.y;
    const int k = split >> 2;
    const int mbase = (split & 3) * MTOT;
    const int row0 = blockIdx.x * BROWS;
    const int cg = tid % (COLS / 8);
    const int rg = tid / (COLS / 8);
    const int r0 = rg * 4, c0 = cg * 8;

    const float* __restrict__ T = Tbuf<COLS>();
    const float* pb = poly + (size_t)k * NN * NN + mbase;
    const float* tb = T + ((size_t)k * NN + mbase) * COLS;

    unsigned long long acc[4][4];
#pragma unroll
    for (int r = 0; r < 4; r++)
#pragma unroll
        for (int c = 0; c < 4; c++) acc[r][c] = 0ull;

    const int mp = tid & 7;   // which m-quad this thread loads
    const int rr = tid >> 3;  // base row for poly loads

    for (int mc = 0; mc < MTOT; mc += MCH) {
        const int mlim = MTOT - mc;  // >= MCH except last chunk (=4, quad aligned)

        // ---- load poly tile (transposed into smem) ----
#pragma unroll
        for (int j = 0; j < BROWS / RSTEP; j++) {
            int r = rr + j * RSTEP;
            int n = row0 + r;
            if (n > NN - 1) n = NN - 1;  // clamp; result discarded at store
            float4 v = make_float4(0.f, 0.f, 0.f, 0.f);
            if (mp * 4 < mlim) v = *(const float4*)(pb + (size_t)n * NN + mc + mp * 4);
            sp[(mp * 4 + 0) * RP + r] = v.x;
            sp[(mp * 4 + 1) * RP + r] = v.y;
            sp[(mp * 4 + 2) * RP + r] = v.z;
            sp[(mp * 4 + 3) * RP + r] = v.w;
        }
        // ---- load T tile (L2-resident) ----
#pragma unroll
        for (int j = 0; j < (MCH * COLS / 4) / THREADS; j++) {
            int idx = tid + j * THREADS;
            int mm = idx / (COLS / 4);
            int cc = (idx % (COLS / 4)) * 4;
            float4 v = make_float4(0.f, 0.f, 0.f, 0.f);
            if (mm < mlim) v = *(const float4*)(tb + (size_t)(mc + mm) * COLS + cc);
            *(float4*)&st[mm * COLS + cc] = v;
        }
        __syncthreads();

        // ---- FFMA2 inner loop: 3 LDS.128 + 16 fma.f32x2 per m ----
#pragma unroll 8
        for (int m = 0; m < MCH; m++) {
            float4 p = *(const float4*)&sp[m * RP + r0];
            ulonglong2 t0 = *(const ulonglong2*)&st[m * COLS + c0];
            ulonglong2 t1 = *(const ulonglong2*)&st[m * COLS + c0 + 4];
            unsigned long long pp;
            pp = pk2(p.x, p.x);
            acc[0][0] = f2(pp, t0.x, acc[0][0]); acc[0][1] = f2(pp, t0.y, acc[0][1]);
            acc[0][2] = f2(pp, t1.x, acc[0][2]); acc[0][3] = f2(pp, t1.y, acc[0][3]);
            pp = pk2(p.y, p.y);
            acc[1][0] = f2(pp, t0.x, acc[1][0]); acc[1][1] = f2(pp, t0.y, acc[1][1]);
            acc[1][2] = f2(pp, t1.x, acc[1][2]); acc[1][3] = f2(pp, t1.y, acc[1][3]);
            pp = pk2(p.z, p.z);
            acc[2][0] = f2(pp, t0.x, acc[2][0]); acc[2][1] = f2(pp, t0.y, acc[2][1]);
            acc[2][2] = f2(pp, t1.x, acc[2][2]); acc[2][3] = f2(pp, t1.y, acc[2][3]);
            pp = pk2(p.w, p.w);
            acc[3][0] = f2(pp, t0.x, acc[3][0]); acc[3][1] = f2(pp, t0.y, acc[3][1]);
            acc[3][2] = f2(pp, t1.x, acc[3][2]); acc[3][3] = f2(pp, t1.y, acc[3][3]);
        }
        __syncthreads();
    }

    // ---- store partials (deterministic; no atomics) ----
    float* pout = Pbuf<COLS>() + (size_t)split * NN * COLS;
#pragma unroll
    for (int r = 0; r < 4; r++) {
        int n = row0 + r0 + r;
        if (n < NN) {
#pragma unroll
            for (int c = 0; c < 4; c++)
                *(unsigned long long*)(pout + (size_t)n * COLS + c0 + c * 2) = acc[r][c];
        }
    }
}

// =======================================================================
// Small GEMM: T[k] = X @ W[k]  (RED=true: X := relu(sum_s P1[s]) on the fly)
// =======================================================================
template <int DOUT, bool RED>
__global__ void __launch_bounds__(32 * (DOUT / 8))
gemm_xw_kernel(const float* __restrict__ X, const float* __restrict__ W) {
    constexpr int DIN = 64, MR = 32;
    constexpr int THREADS = MR * (DOUT / 8);
    __shared__ float Ws[DIN * DOUT];
    __shared__ float Xs[MR * (DIN + 1)];
    const int tid = threadIdx.x;
    const int k = blockIdx.y;
    const int m0 = blockIdx.x * MR;

    for (int i = tid; i < DIN * DOUT; i += THREADS)
        Ws[i] = W[(size_t)k * DIN * DOUT + i];
    for (int i = tid; i < MR * DIN; i += THREADS) {
        int r = i >> 6, d = i & 63;
        int n = m0 + r;
        if (n > NN - 1) n = NN - 1;
        float v;
        if (!RED) {
            v = X[(size_t)n * DIN + d];
        } else {
            v = 0.f;
#pragma unroll
            for (int s = 0; s < SPLITS; s++) v += g_P1[((size_t)s * NN + n) * DIN + d];
            v = fmaxf(v, 0.f);  // fused ReLU of layer-0 output
        }
        Xs[r * (DIN + 1) + d] = v;
    }
    __syncthreads();

    const int row = tid / (DOUT / 8);
    const int c0 = (tid % (DOUT / 8)) * 8;
    float a[8];
#pragma unroll
    for (int c = 0; c < 8; c++) a[c] = 0.f;

#pragma unroll
    for (int d = 0; d < DIN; d++) {
        float xv = Xs[row * (DIN + 1) + d];
        float4 wa = *(const float4*)&Ws[d * DOUT + c0];
        float4 wb = *(const float4*)&Ws[d * DOUT + c0 + 4];
        a[0] = fmaf(xv, wa.x, a[0]); a[1] = fmaf(xv, wa.y, a[1]);
        a[2] = fmaf(xv, wa.z, a[2]); a[3] = fmaf(xv, wa.w, a[3]);
        a[4] = fmaf(xv, wb.x, a[4]); a[5] = fmaf(xv, wb.y, a[5]);
        a[6] = fmaf(xv, wb.z, a[6]); a[7] = fmaf(xv, wb.w, a[7]);
    }
    int n = m0 + row;
    if (n < NN) {
        float* T = Tbuf<DOUT>() + ((size_t)k * NN + n) * DOUT + c0;
        *(float4*)T = make_float4(a[0], a[1], a[2], a[3]);
        *(float4*)(T + 4) = make_float4(a[4], a[5], a[6], a[7]);
    }
}

// Final reduction of layer-1 partials into d_out (poisoned buffer -> full overwrite)
__global__ void reduce_out_kernel(float* __restrict__ out) {
    int i = blockIdx.x * blockDim.x + threadIdx.x;
    if (i < NN * 32 / 4) {
        float4 a = make_float4(0.f, 0.f, 0.f, 0.f);
#pragma unroll
        for (int s = 0; s < SPLITS; s++) {
            float4 v = *(const float4*)(g_P2 + (size_t)s * NN * 32 + (size_t)i * 4);
            a.x += v.x; a.y += v.y; a.z += v.z; a.w += v.w;
        }
        *(float4*)(out + (size_t)i * 4) = a;
    }
}

extern "C" void kernel_launch(void* const* d_in, const int* in_sizes, int n_in,
                              void* d_out, int out_size) {
    const float* x    = (const float*)d_in[0];
    const float* poly = (const float*)d_in[1];
    const float* W1   = (const float*)d_in[2];
    const float* W2   = (const float*)d_in[3];
    float* out = (float*)d_out;

    dim3 gm((NN + 31) / 32, KPOLY);
    dim3 gp((NN + 127) / 128, SPLITS);

    gemm_xw_kernel<64, false><<<gm, 256>>>(x, W1);   // T1 = x @ W1[k]
    poly_apply_kernel<64><<<gp, 256>>>(poly);        // P1[s] = poly_s @ T1_s
    gemm_xw_kernel<32, true><<<gm, 128>>>(x, W2);    // T2 = relu(sum P1) @ W2[k]
    poly_apply_kernel<32><<<gp, 128>>>(poly);        // P2[s] = poly_s @ T2_s
    reduce_out_kernel<<<(NN * 32 / 4 + 255) / 256, 256>>>(out);
}

// round 3
// speedup vs baseline: 1.7686x; 1.7686x over previous
#include <cuda_runtime.h>
#include <cuda_bf16.h>
#include <mma.h>
#include <cstdint>

using namespace nvcuda;

#define KPOLY 3
#define NN 10000
#define SPLITS 12           // 3 polys x 4 K-quarters
#define KSPL 2560           // K per split (last split: 2320) — 64-aligned boundaries
#define KCH 64
#define MTILE 128
#define MT ((NN + MTILE - 1) / MTILE)  // 79

// ---------------- scratch (static device arrays; no allocation) ----------------
__device__ unsigned short g_T1h[(size_t)64 * KPOLY * NN];  // T1^T hi  [c][k][m]
__device__ unsigned short g_T1l[(size_t)64 * KPOLY * NN];  // T1^T lo
__device__ unsigned short g_T2h[(size_t)32 * KPOLY * NN];
__device__ unsigned short g_T2l[(size_t)32 * KPOLY * NN];
__device__ float g_P1[(size_t)SPLITS * NN * 64];
__device__ float g_P2[(size_t)SPLITS * NN * 32];

template <int C> __device__ __forceinline__ const unsigned short* TH() {
    if constexpr (C == 64) return g_T1h; else return g_T2h;
}
template <int C> __device__ __forceinline__ const unsigned short* TL() {
    if constexpr (C == 64) return g_T1l; else return g_T2l;
}
template <int C> __device__ __forceinline__ float* PB() {
    if constexpr (C == 64) return g_P1; else return g_P2;
}

__device__ __forceinline__ uint32_t smem_u32(const void* p) {
    uint32_t a;
    asm("{ .reg .u64 t; cvta.to.shared.u64 t, %1; cvt.u32.u64 %0, t; }" : "=r"(a) : "l"(p));
    return a;
}

// exact two-term split: x = hi + lo (hi = RNE bf16 of x); hi2 packs two hi's
__device__ __forceinline__ void split2(float x, float y, uint32_t& hi2, float& lx, float& ly) {
    uint32_t ux = __float_as_uint(x);
    uint32_t rx = (ux + 0x7FFFu + ((ux >> 16) & 1u)) & 0xFFFF0000u;
    uint32_t uy = __float_as_uint(y);
    uint32_t ry = (uy + 0x7FFFu + ((uy >> 16) & 1u)) & 0xFFFF0000u;
    hi2 = (rx >> 16) | (ry & 0xFFFF0000u);
    lx = x - __uint_as_float(rx);
    ly = y - __uint_as_float(ry);
}
__device__ __forceinline__ uint32_t pkbf(float a, float b) {  // a -> low 16 bits
    uint32_t r;
    asm("cvt.rn.bf16x2.f32 %0, %1, %2;" : "=r"(r) : "f"(b), "f"(a));
    return r;
}

#define CP_ASYNC(dst, src, pb) \
    asm volatile("cp.async.cg.shared.global [%0], [%1], 16, %2;" \
        :: "r"(dst), "l"(src), "r"(pb) : "memory")
#define CP_COMMIT() asm volatile("cp.async.commit_group;" ::: "memory")
#define CP_WAIT0()  asm volatile("cp.async.wait_group 0;" ::: "memory")

// =======================================================================
// poly MMA kernel: P[split] = poly_slice @ T_slice (WMMA bf16, 3-pass split)
// CTA: 128 rows x C cols; 8 warps, warp = 16 rows x C; K chunk 64.
// =======================================================================
template <int C>
__global__ void __launch_bounds__(256, 2)
poly_mma_kernel(const float* __restrict__ poly) {
    extern __shared__ __align__(128) char smem[];
    constexpr int LD = 72;                 // padded ld: LDSM conflict-free
    constexpr int ABYT = MTILE * LD * 2;   // 18432 per A operand
    constexpr int BBYT = C * LD * 2;       // 9216 / 4608
    constexpr int SS = 2 * ABYT + 2 * BBYT;
    constexpr int NT = C / 16;
    constexpr int BOPS = C * 8 / 256;      // cp.async (16B) per thread per operand

    const int tid = threadIdx.x;
    const int warp = tid >> 5;
    const int split = blockIdx.y;
    const int k = split >> 2;
    const int mbase = (split & 3) * KSPL;
    const int klen = (NN - mbase < KSPL) ? (NN - mbase) : KSPL;
    const int nch = (klen + KCH - 1) / KCH;
    const int row0 = blockIdx.x * MTILE;
    const uint32_t sb = smem_u32(smem);

    // ---- A (poly) per-thread source: row = tid>>1, half = (tid&1)*32 ----
    int arow = row0 + (tid >> 1);
    if (arow > NN - 1) arow = NN - 1;  // clamp; clamped rows discarded at store
    const float* abase = poly + (size_t)k * NN * NN + (size_t)arow * NN + mbase;
    const int chalf = (tid & 1) * 32;

    // ---- B (T hi/lo) cp.async fixed addressing ----
    const unsigned short* bhs[BOPS];
    const unsigned short* bls[BOPS];
    uint32_t bdst[BOPS];
    int bk8[BOPS];
#pragma unroll
    for (int j = 0; j < BOPS; j++) {
        int idx = tid + j * 256;
        int c = idx >> 3, k8 = (idx & 7) * 8;
        size_t off = ((size_t)c * KPOLY + k) * NN + mbase + k8;
        bhs[j] = TH<C>() + off;
        bls[j] = TL<C>() + off;
        bdst[j] = (uint32_t)((c * LD + k8) * 2);
        bk8[j] = k8;
    }

    float4 a[8];
    auto loadA = [&](int mc) {
        const int kv = klen - mc;
#pragma unroll
        for (int j = 0; j < 8; j++) {
            int cc = chalf + j * 4;
            if (cc < kv) a[j] = *(const float4*)(abase + mc + cc);
            else a[j] = make_float4(0.f, 0.f, 0.f, 0.f);
        }
    };

    wmma::fragment<wmma::accumulator, 16, 16, 16, float> acc[NT];
#pragma unroll
    for (int n = 0; n < NT; n++) wmma::fill_fragment(acc[n], 0.0f);

    loadA(0);

    for (int ch = 0; ch < nch; ch++) {
        const int s = ch & 1;
        const int mc = ch * KCH;
        char* Ah = smem + s * SS;
        char* Al = Ah + ABYT;
        const uint32_t bh0 = sb + s * SS + 2 * ABYT;
        const uint32_t bl0 = bh0 + BBYT;

        // store A hi/lo (fp32 -> exact bf16 two-term split)
        {
            const int r = tid >> 1;
#pragma unroll
            for (int j = 0; j < 8; j++) {
                int c = chalf + j * 4;
                float4 v = a[j];
                uint32_t h0, h1;
                float l0, l1, l2, l3;
                split2(v.x, v.y, h0, l0, l1);
                split2(v.z, v.w, h1, l2, l3);
                *(uint2*)(Ah + (r * LD + c) * 2) = make_uint2(h0, h1);
                *(uint2*)(Al + (r * LD + c) * 2) = make_uint2(pkbf(l0, l1), pkbf(l2, l3));
            }
        }
        // B via cp.async (zero-fill beyond klen)
        {
            const int kv = klen - mc;
#pragma unroll
            for (int j = 0; j < BOPS; j++) {
                const int pb = (bk8[j] < kv) ? 16 : 0;
                const unsigned short* sh = pb ? (bhs[j] + mc) : bhs[j];
                const unsigned short* sl = pb ? (bls[j] + mc) : bls[j];
                CP_ASYNC(bh0 + bdst[j], sh, pb);
                CP_ASYNC(bl0 + bdst[j], sl, pb);
            }
            CP_COMMIT();
        }
        if (ch + 1 < nch) loadA((ch + 1) * KCH);
        CP_WAIT0();
        __syncthreads();

        // compute on stage s
        const __nv_bfloat16* Ahp = (const __nv_bfloat16*)(smem + s * SS);
        const __nv_bfloat16* Alp = Ahp + MTILE * LD;
        const __nv_bfloat16* Bhp = (const __nv_bfloat16*)(smem + s * SS + 2 * ABYT);
        const __nv_bfloat16* Blp = Bhp + C * LD;
        wmma::fragment<wmma::matrix_a, 16, 16, 16, __nv_bfloat16, wmma::row_major> fah, fal;
        wmma::fragment<wmma::matrix_b, 16, 16, 16, __nv_bfloat16, wmma::col_major> fbh, fbl;
#pragma unroll
        for (int k4 = 0; k4 < 4; k4++) {
            wmma::load_matrix_sync(fah, Ahp + warp * 16 * LD + k4 * 16, LD);
            wmma::load_matrix_sync(fal, Alp + warp * 16 * LD + k4 * 16, LD);
#pragma unroll
            for (int n = 0; n < NT; n++) {
                wmma::load_matrix_sync(fbh, Bhp + n * 16 * LD + k4 * 16, LD);
                wmma::load_matrix_sync(fbl, Blp + n * 16 * LD + k4 * 16, LD);
                wmma::mma_sync(acc[n], fah, fbh, acc[n]);
                wmma::mma_sync(acc[n], fah, fbl, acc[n]);
                wmma::mma_sync(acc[n], fal, fbh, acc[n]);
            }
        }
    }

    // store partials (deterministic; per-warp tile fully valid or fully invalid:
    // NN - 78*128 = 16 = one warp tile)
    const int nrow = row0 + warp * 16;
    if (nrow < NN) {
        float* o = PB<C>() + ((size_t)split * NN + nrow) * C;
#pragma unroll
        for (int n = 0; n < NT; n++)
            wmma::store_matrix_sync(o + n * 16, acc[n], C, wmma::mem_row_major);
    }
}

// =======================================================================
// Small GEMM: Tt[c][k][n] = (X @ W[k])[n][c] split into bf16 hi/lo.
// RED: X := relu(sum_s P1[s]) read on the fly.
// =======================================================================
template <int DOUT, bool RED>
__global__ void __launch_bounds__(256)
gemm_xw_kernel(const float* __restrict__ X, const float* __restrict__ W,
               unsigned short* __restrict__ Th, unsigned short* __restrict__ Tl) {
    constexpr int DIN = 64;
    constexpr int MR = 256 / (DOUT / 8);  // 32 (DOUT=64) or 64 (DOUT=32)
    __shared__ float Ws[DIN * DOUT];
    __shared__ float Xs[MR * (DIN + 1)];
    const int tid = threadIdx.x;
    const int kb = blockIdx.y;
    const int m0 = blockIdx.x * MR;

    for (int i = tid; i < DIN * DOUT; i += 256)
        Ws[i] = W[(size_t)kb * DIN * DOUT + i];
    for (int i = tid; i < MR * DIN; i += 256) {
        int r = i >> 6, d = i & 63;
        int n = m0 + r;
        if (n > NN - 1) n = NN - 1;
        float v;
        if (!RED) {
            v = X[(size_t)n * DIN + d];
        } else {
            v = 0.f;
#pragma unroll
            for (int s = 0; s < SPLITS; s++) v += g_P1[((size_t)s * NN + n) * 64 + d];
            v = fmaxf(v, 0.f);
        }
        Xs[r * (DIN + 1) + d] = v;
    }
    __syncthreads();

    const int row = tid % MR;
    const int c0 = (tid / MR) * 8;
    float a[8];
#pragma unroll
    for (int c = 0; c < 8; c++) a[c] = 0.f;
#pragma unroll
    for (int d = 0; d < DIN; d++) {
        float xv = Xs[row * (DIN + 1) + d];
        float4 wa = *(const float4*)&Ws[d * DOUT + c0];
        float4 wb = *(const float4*)&Ws[d * DOUT + c0 + 4];
        a[0] = fmaf(xv, wa.x, a[0]); a[1] = fmaf(xv, wa.y, a[1]);
        a[2] = fmaf(xv, wa.z, a[2]); a[3] = fmaf(xv, wa.w, a[3]);
        a[4] = fmaf(xv, wb.x, a[4]); a[5] = fmaf(xv, wb.y, a[5]);
        a[6] = fmaf(xv, wb.z, a[6]); a[7] = fmaf(xv, wb.w, a[7]);
    }
    const int n = m0 + row;
    if (n < NN) {
#pragma unroll
        for (int c = 0; c < 8; c++) {
            float v = a[c];
            uint32_t u = __float_as_uint(v);
            uint32_t r = (u + 0x7FFFu + ((u >> 16) & 1u)) & 0xFFFF0000u;
            float lof = v - __uint_as_float(r);
            unsigned short ls;
            asm("cvt.rn.bf16.f32 %0, %1;" : "=h"(ls) : "f"(lof));
            size_t idx = ((size_t)(c0 + c) * KPOLY + kb) * NN + n;
            Th[idx] = (unsigned short)(r >> 16);
            Tl[idx] = ls;
        }
    }
}

// Final reduction of layer-1 partials into d_out
__global__ void reduce_out_kernel(float* __restrict__ out) {
    int i = blockIdx.x * blockDim.x + threadIdx.x;
    if (i < NN * 32 / 4) {
        float4 acc = make_float4(0.f, 0.f, 0.f, 0.f);
#pragma unroll
        for (int s = 0; s < SPLITS; s++) {
            float4 v = *(const float4*)(g_P2 + (size_t)s * NN * 32 + (size_t)i * 4);
            acc.x += v.x; acc.y += v.y; acc.z += v.z; acc.w += v.w;
        }
        *(float4*)(out + (size_t)i * 4) = acc;
    }
}

extern "C" void kernel_launch(void* const* d_in, const int* in_sizes, int n_in,
                              void* d_out, int out_size) {
    const float* x    = (const float*)d_in[0];
    const float* poly = (const float*)d_in[1];
    const float* W1   = (const float*)d_in[2];
    const float* W2   = (const float*)d_in[3];
    float* out = (float*)d_out;

    constexpr int SMEM64 = 2 * (2 * (MTILE * 72 * 2) + 2 * (64 * 72 * 2));  // 110592
    constexpr int SMEM32 = 2 * (2 * (MTILE * 72 * 2) + 2 * (32 * 72 * 2));  // 92160
    static bool configured = false;
    if (!configured) {
        cudaFuncSetAttribute((const void*)poly_mma_kernel<64>,
                             cudaFuncAttributeMaxDynamicSharedMemorySize, SMEM64);
        cudaFuncSetAttribute((const void*)poly_mma_kernel<32>,
                             cudaFuncAttributeMaxDynamicSharedMemorySize, SMEM32);
        configured = true;
    }

    unsigned short *T1h, *T1l, *T2h, *T2l;
    cudaGetSymbolAddress((void**)&T1h, g_T1h);
    cudaGetSymbolAddress((void**)&T1l, g_T1l);
    cudaGetSymbolAddress((void**)&T2h, g_T2h);
    cudaGetSymbolAddress((void**)&T2l, g_T2l);

    dim3 g1((NN + 31) / 32, KPOLY);
    dim3 g2((NN + 63) / 64, KPOLY);
    dim3 gp(MT, SPLITS);

    gemm_xw_kernel<64, false><<<g1, 256>>>(x, W1, T1h, T1l);  // T1^T hi/lo
    poly_mma_kernel<64><<<gp, 256, SMEM64>>>(poly);           // P1 = poly @ T1 (split-K)
    gemm_xw_kernel<32, true><<<g2, 256>>>(x, W2, T2h, T2l);   // T2^T = relu(sum P1) @ W2
    poly_mma_kernel<32><<<gp, 256, SMEM32>>>(poly);           // P2 = poly @ T2
    reduce_out_kernel<<<(NN * 32 / 4 + 255) / 256, 256>>>(out);
}

// round 4
// speedup vs baseline: 1.8520x; 1.0472x over previous
#include <cuda_runtime.h>
#include <cuda_bf16.h>
#include <mma.h>
#include <cstdint>

using namespace nvcuda;

#define KPOLY 3
#define NN 10000
#define SPLITS 12           // 3 polys x 4 K-quarters
#define KSPL 2560           // K per split (last: 2320); 64-aligned boundaries
#define KCH 32
#define MTILE 128
#define MT ((NN + MTILE - 1) / MTILE)  // 79

// ---------------- scratch (static device arrays; no allocation) ----------------
__device__ __align__(16) unsigned short g_T1h[(size_t)64 * KPOLY * NN];
__device__ __align__(16) unsigned short g_T1l[(size_t)64 * KPOLY * NN];
__device__ __align__(16) unsigned short g_T2h[(size_t)32 * KPOLY * NN];
__device__ __align__(16) unsigned short g_T2l[(size_t)32 * KPOLY * NN];
__device__ __align__(16) unsigned short g_Ah[(size_t)KPOLY * NN * NN];  // presplit poly hi
__device__ __align__(16) unsigned short g_Al[(size_t)KPOLY * NN * NN];  // presplit poly lo
__device__ float g_P1[(size_t)SPLITS * NN * 64];
__device__ float g_P2[(size_t)SPLITS * NN * 32];

__device__ __forceinline__ uint32_t smem_u32(const void* p) {
    uint32_t a;
    asm("{ .reg .u64 t; cvta.to.shared.u64 t, %1; cvt.u32.u64 %0, t; }" : "=r"(a) : "l"(p));
    return a;
}

// exact two-term split: x = hi + lo (hi = RNE bf16 of x); hi2 packs two hi's
__device__ __forceinline__ void split2(float x, float y, uint32_t& hi2, float& lx, float& ly) {
    uint32_t ux = __float_as_uint(x);
    uint32_t rx = (ux + 0x7FFFu + ((ux >> 16) & 1u)) & 0xFFFF0000u;
    uint32_t uy = __float_as_uint(y);
    uint32_t ry = (uy + 0x7FFFu + ((uy >> 16) & 1u)) & 0xFFFF0000u;
    hi2 = (rx >> 16) | (ry & 0xFFFF0000u);
    lx = x - __uint_as_float(rx);
    ly = y - __uint_as_float(ry);
}
__device__ __forceinline__ uint32_t pkbf(float a, float b) {  // a -> low 16 bits
    uint32_t r;
    asm("cvt.rn.bf16x2.f32 %0, %1, %2;" : "=r"(r) : "f"(b), "f"(a));
    return r;
}

#define CP_ASYNC(dst, src, pb) \
    asm volatile("cp.async.cg.shared.global [%0], [%1], 16, %2;" \
        :: "r"(dst), "l"(src), "r"(pb) : "memory")
#define CP_COMMIT() asm volatile("cp.async.commit_group;" ::: "memory")
#define CP_WAIT1()  asm volatile("cp.async.wait_group 1;" ::: "memory")

// =======================================================================
// poly MMA kernel: P[split] = poly_slice @ T_slice
// 3-stage smem pipeline; KCH=32; pass-major MMA; PRE => A from presplit
// global bf16 planes via cp.async (no fp32 load / no split ALU).
// =======================================================================
template <int C, bool PRE>
__global__ void __launch_bounds__(256, PRE ? 3 : 2)
poly_mma_kernel(const float* __restrict__ poly,
                const unsigned short* __restrict__ Bhg,
                const unsigned short* __restrict__ Blg,
                unsigned short* __restrict__ Ahg,
                unsigned short* __restrict__ Alg,
                float* __restrict__ P) {
    constexpr int LDA = PRE ? 32 : 40;     // 40: conflict-free STS/LDSM; 32: compact
    constexpr int LDB = 40;
    constexpr int ABYT = MTILE * LDA * 2;  // one A plane per stage
    constexpr int BBYT = C * LDB * 2;
    constexpr int SS = 2 * ABYT + 2 * BBYT;
    constexpr int NT = C / 16;
    extern __shared__ __align__(128) char smem[];
    const uint32_t sb = smem_u32(smem);

    const int tid = threadIdx.x;
    const int warp = tid >> 5;
    const int split = blockIdx.y;
    const int k = split >> 2;
    const int mbase = (split & 3) * KSPL;
    const int klen = min(NN - mbase, KSPL);
    const int nch = (klen + KCH - 1) / KCH;
    const int row0 = blockIdx.x * MTILE;

    // ---- B cp.async addressing (plane C x 32 per chunk; 16B per lane) ----
    const int bc = tid >> 2, bk8 = (tid & 3) * 8;
    const unsigned short* bsrcH = Bhg + ((size_t)bc * KPOLY + k) * NN + mbase + bk8;
    const unsigned short* bsrcL = Blg + ((size_t)bc * KPOLY + k) * NN + mbase + bk8;
    const uint32_t bdoff = (uint32_t)((bc * LDB + bk8) * 2);

    auto issueB = [&](int ch) {
        const int mc = ch * KCH;
        const int kv = klen - mc;
        if (C == 64 || tid < 128) {
            const int pb = (bk8 < kv) ? 16 : 0;
            const unsigned short* sh = pb ? (bsrcH + mc) : bsrcH;
            const unsigned short* sl = pb ? (bsrcL + mc) : bsrcL;
            const uint32_t d = sb + ((ch % 3) * SS + 2 * ABYT) + bdoff;
            CP_ASYNC(d, sh, pb);
            CP_ASYNC(d + BBYT, sl, pb);
        }
    };

    // ---- A addressing ----
    // PRE: cp.async 2x16B per plane per thread
    const int ar2 = tid >> 2, ak8 = (tid & 3) * 8;
    const unsigned short* asrcH[2];
    const unsigned short* asrcL[2];
    uint32_t adoff[2];
#pragma unroll
    for (int q = 0; q < 2; q++) {
        const int r = ar2 + q * 64;
        const int arow = min(row0 + r, NN - 1);
        asrcH[q] = Ahg + ((size_t)k * NN + arow) * NN + mbase + ak8;
        asrcL[q] = Alg + ((size_t)k * NN + arow) * NN + mbase + ak8;
        adoff[q] = (uint32_t)((r * LDA + ak8) * 2);
    }
    auto issueA = [&](int ch) {
        const int mc = ch * KCH;
        const int kv = klen - mc;
        const int pb = (ak8 < kv) ? 16 : 0;
        const uint32_t base = sb + (ch % 3) * SS;
#pragma unroll
        for (int q = 0; q < 2; q++) {
            const unsigned short* sh = pb ? (asrcH[q] + mc) : asrcH[q];
            const unsigned short* sl = pb ? (asrcL[q] + mc) : asrcL[q];
            CP_ASYNC(base + adoff[q], sh, pb);
            CP_ASYNC(base + ABYT + adoff[q], sl, pb);
        }
    };

    // !PRE: fp32 LDG prefetch + split + STS + presplit STG
    const int lrow = tid >> 1;
    const int ch16 = (tid & 1) * 16;
    const int larow = min(row0 + lrow, NN - 1);
    const float* abase = poly + (size_t)k * NN * NN + (size_t)larow * NN + mbase;
    unsigned short* agH = Ahg + ((size_t)k * NN + larow) * NN + mbase;
    unsigned short* agL = Alg + ((size_t)k * NN + larow) * NN + mbase;

    float4 a[4];
    auto loadA = [&](int ch) {
        const int mc = ch * KCH;
        const int kv = klen - mc;
#pragma unroll
        for (int j = 0; j < 4; j++) {
            const int cc = ch16 + j * 4;
            if (cc < kv) a[j] = *(const float4*)(abase + mc + cc);
            else a[j] = make_float4(0.f, 0.f, 0.f, 0.f);
        }
    };
    auto storeA = [&](int ch) {  // split regs -> STS stage(ch%3) + STG presplit
        const int mc = ch * KCH;
        const int kv = klen - mc;
        char* Ah = smem + (ch % 3) * SS;
        char* Al = Ah + ABYT;
        uint32_t h[8], lp[8];
#pragma unroll
        for (int j = 0; j < 4; j++) {
            float l0, l1, l2, l3;
            split2(a[j].x, a[j].y, h[2 * j], l0, l1);
            split2(a[j].z, a[j].w, h[2 * j + 1], l2, l3);
            lp[2 * j] = pkbf(l0, l1);
            lp[2 * j + 1] = pkbf(l2, l3);
            const int c = ch16 + j * 4;
            *(uint2*)(Ah + (lrow * LDA + c) * 2) = make_uint2(h[2 * j], h[2 * j + 1]);
            *(uint2*)(Al + (lrow * LDA + c) * 2) = make_uint2(lp[2 * j], lp[2 * j + 1]);
        }
#pragma unroll
        for (int jp = 0; jp < 2; jp++) {
            const int cc = ch16 + jp * 8;
            if (cc < kv) {  // kv multiple of 16 => full 8-col store valid
                *(uint4*)(agH + mc + cc) = make_uint4(h[4 * jp], h[4 * jp + 1], h[4 * jp + 2], h[4 * jp + 3]);
                *(uint4*)(agL + mc + cc) = make_uint4(lp[4 * jp], lp[4 * jp + 1], lp[4 * jp + 2], lp[4 * jp + 3]);
            }
        }
    };

    // ---- accumulators ----
    wmma::fragment<wmma::accumulator, 16, 16, 16, float> acc[NT];
#pragma unroll
    for (int n = 0; n < NT; n++) wmma::fill_fragment(acc[n], 0.0f);

    auto domma = [&](int ch) {
        const __nv_bfloat16* Ahp = (const __nv_bfloat16*)(smem + (ch % 3) * SS);
        const __nv_bfloat16* Alp = Ahp + MTILE * LDA;
        const __nv_bfloat16* Bhp = (const __nv_bfloat16*)(smem + (ch % 3) * SS + 2 * ABYT);
        const __nv_bfloat16* Blp = Bhp + C * LDB;
#pragma unroll
        for (int ks = 0; ks < 2; ks++) {
            wmma::fragment<wmma::matrix_a, 16, 16, 16, __nv_bfloat16, wmma::row_major> fah, fal;
            wmma::load_matrix_sync(fah, Ahp + warp * 16 * LDA + ks * 16, LDA);
            wmma::load_matrix_sync(fal, Alp + warp * 16 * LDA + ks * 16, LDA);
            wmma::fragment<wmma::matrix_b, 16, 16, 16, __nv_bfloat16, wmma::col_major> fbh[NT];
#pragma unroll
            for (int n = 0; n < NT; n++)
                wmma::load_matrix_sync(fbh[n], Bhp + n * 16 * LDB + ks * 16, LDB);
#pragma unroll
            for (int n = 0; n < NT; n++) wmma::mma_sync(acc[n], fah, fbh[n], acc[n]);
            {
                wmma::fragment<wmma::matrix_b, 16, 16, 16, __nv_bfloat16, wmma::col_major> fbl;
#pragma unroll
                for (int n = 0; n < NT; n++) {
                    wmma::load_matrix_sync(fbl, Blp + n * 16 * LDB + ks * 16, LDB);
                    wmma::mma_sync(acc[n], fah, fbl, acc[n]);
                }
            }
#pragma unroll
            for (int n = 0; n < NT; n++) wmma::mma_sync(acc[n], fal, fbh[n], acc[n]);
        }
    };

    // ---- prologue ----
    if (!PRE) loadA(0);
    issueB(0); if (PRE) issueA(0);
    CP_COMMIT();
    issueB(1); if (PRE) issueA(1);
    CP_COMMIT();
    if (!PRE) { storeA(0); loadA(1); }

    // ---- mainloop: compute ch; STS ch+1; async ch+2 ----
    for (int ch = 0; ch < nch; ch++) {
        if (!PRE) {
            storeA(ch + 1);        // stage (ch+1)%3 == (ch-2)%3: safe (MMA(ch-2) done)
            loadA(ch + 2);
        }
        CP_WAIT1();                // group(ch) complete
        __syncthreads();           // STS(ch) visible; all warps past MMA(ch-1)
        issueB(ch + 2); if (PRE) issueA(ch + 2);
        CP_COMMIT();
        domma(ch);
    }

    // ---- store partials (warp tile fully valid or fully invalid: 10000-9984=16) ----
    const int nrow = row0 + warp * 16;
    if (nrow < NN) {
        float* o = P + ((size_t)split * NN + nrow) * C;
#pragma unroll
        for (int n = 0; n < NT; n++)
            wmma::store_matrix_sync(o + n * 16, acc[n], C, wmma::mem_row_major);
    }
}

// =======================================================================
// Small GEMM: Tt[c][k][n] = (X @ W[k])[n][c] split into bf16 hi/lo.
// RED: X := relu(sum_s P1[s]) read on the fly.
// =======================================================================
template <int DOUT, bool RED>
__global__ void __launch_bounds__(256)
gemm_xw_kernel(const float* __restrict__ X, const float* __restrict__ W,
               unsigned short* __restrict__ Th, unsigned short* __restrict__ Tl) {
    constexpr int DIN = 64;
    constexpr int MR = 256 / (DOUT / 8);
    __shared__ float Ws[DIN * DOUT];
    __shared__ float Xs[MR * (DIN + 1)];
    const int tid = threadIdx.x;
    const int kb = blockIdx.y;
    const int m0 = blockIdx.x * MR;

    for (int i = tid; i < DIN * DOUT; i += 256)
        Ws[i] = W[(size_t)kb * DIN * DOUT + i];
    for (int i = tid; i < MR * DIN; i += 256) {
        int r = i >> 6, d = i & 63;
        int n = m0 + r;
        if (n > NN - 1) n = NN - 1;
        float v;
        if (!RED) {
            v = X[(size_t)n * DIN + d];
        } else {
            v = 0.f;
#pragma unroll
            for (int s = 0; s < SPLITS; s++) v += g_P1[((size_t)s * NN + n) * 64 + d];
            v = fmaxf(v, 0.f);
        }
        Xs[r * (DIN + 1) + d] = v;
    }
    __syncthreads();

    const int row = tid % MR;
    const int c0 = (tid / MR) * 8;
    float a[8];
#pragma unroll
    for (int c = 0; c < 8; c++) a[c] = 0.f;
#pragma unroll
    for (int d = 0; d < DIN; d++) {
        float xv = Xs[row * (DIN + 1) + d];
        float4 wa = *(const float4*)&Ws[d * DOUT + c0];
        float4 wb = *(const float4*)&Ws[d * DOUT + c0 + 4];
        a[0] = fmaf(xv, wa.x, a[0]); a[1] = fmaf(xv, wa.y, a[1]);
        a[2] = fmaf(xv, wa.z, a[2]); a[3] = fmaf(xv, wa.w, a[3]);
        a[4] = fmaf(xv, wb.x, a[4]); a[5] = fmaf(xv, wb.y, a[5]);
        a[6] = fmaf(xv, wb.z, a[6]); a[7] = fmaf(xv, wb.w, a[7]);
    }
    const int n = m0 + row;
    if (n < NN) {
#pragma unroll
        for (int c = 0; c < 8; c++) {
            float v = a[c];
            uint32_t u = __float_as_uint(v);
            uint32_t r = (u + 0x7FFFu + ((u >> 16) & 1u)) & 0xFFFF0000u;
            float lof = v - __uint_as_float(r);
            unsigned short ls;
            asm("cvt.rn.bf16.f32 %0, %1;" : "=h"(ls) : "f"(lof));
            size_t idx = ((size_t)(c0 + c) * KPOLY + kb) * NN + n;
            Th[idx] = (unsigned short)(r >> 16);
            Tl[idx] = ls;
        }
    }
}

// Final reduction of layer-1 partials into d_out
__global__ void reduce_out_kernel(float* __restrict__ out) {
    int i = blockIdx.x * blockDim.x + threadIdx.x;
    if (i < NN * 32 / 4) {
        float4 acc = make_float4(0.f, 0.f, 0.f, 0.f);
#pragma unroll
        for (int s = 0; s < SPLITS; s++) {
            float4 v = *(const float4*)(g_P2 + (size_t)s * NN * 32 + (size_t)i * 4);
            acc.x += v.x; acc.y += v.y; acc.z += v.z; acc.w += v.w;
        }
        *(float4*)(out + (size_t)i * 4) = acc;
    }
}

extern "C" void kernel_launch(void* const* d_in, const int* in_sizes, int n_in,
                              void* d_out, int out_size) {
    const float* x    = (const float*)d_in[0];
    const float* poly = (const float*)d_in[1];
    const float* W1   = (const float*)d_in[2];
    const float* W2   = (const float*)d_in[3];
    float* out = (float*)d_out;

    constexpr int SMEM64 = 3 * (2 * (MTILE * 40 * 2) + 2 * (64 * 40 * 2));  // 92160
    constexpr int SMEM32 = 3 * (2 * (MTILE * 32 * 2) + 2 * (32 * 40 * 2));  // 64512
    cudaFuncSetAttribute((const void*)poly_mma_kernel<64, false>,
                         cudaFuncAttributeMaxDynamicSharedMemorySize, SMEM64);
    cudaFuncSetAttribute((const void*)poly_mma_kernel<32, true>,
                         cudaFuncAttributeMaxDynamicSharedMemorySize, SMEM32);

    unsigned short *T1h, *T1l, *T2h, *T2l, *Ah, *Al;
    float *P1, *P2;
    cudaGetSymbolAddress((void**)&T1h, g_T1h);
    cudaGetSymbolAddress((void**)&T1l, g_T1l);
    cudaGetSymbolAddress((void**)&T2h, g_T2h);
    cudaGetSymbolAddress((void**)&T2l, g_T2l);
    cudaGetSymbolAddress((void**)&Ah, g_Ah);
    cudaGetSymbolAddress((void**)&Al, g_Al);
    cudaGetSymbolAddress((void**)&P1, g_P1);
    cudaGetSymbolAddress((void**)&P2, g_P2);

    dim3 g1((NN + 31) / 32, KPOLY);
    dim3 g2((NN + 63) / 64, KPOLY);
    dim3 gp(MT, SPLITS);

    gemm_xw_kernel<64, false><<<g1, 256>>>(x, W1, T1h, T1l);
    poly_mma_kernel<64, false><<<gp, 256, SMEM64>>>(poly, T1h, T1l, Ah, Al, P1);
    gemm_xw_kernel<32, true><<<g2, 256>>>(x, W2, T2h, T2l);
    poly_mma_kernel<32, true><<<gp, 256, SMEM32>>>(poly, T2h, T2l, Ah, Al, P2);
    reduce_out_kernel<<<(NN * 32 / 4 + 255) / 256, 256>>>(out);
}